// round 13
// baseline (speedup 1.0000x reference)
#include <cuda_runtime.h>
#include <cuda_bf16.h>
#include <cuda_fp16.h>
#include <mma.h>
#include <cstdint>

using namespace nvcuda;

#define B_SZ 65536
#define D_SZ 256
#define F_SZ 512
#define P_SZ 256

// padded smem strides — all row strides odd in 16B units => conflict-free
#define RS_LD  520   // bf16: 1040B = 65 units
#define XS_LD  264   // fp16: 528B  = 33 units
#define OS_LD  260   // fp32: 1040B = 65 units
#define PS_LD  260   // pside fp32

// ---------------- scratch (static device globals; no allocations) ----------------
// Packed B-fragment layout for mma.sync m16n8k16 (row.col):
//   [nb][kb][lane] -> uint2 ; reg r of lane l holds  M[n = nb*8 + l/4][k = kb*16 + (l%4)*2 + 8r .. +1]
__device__ uint2  g_W1p[(P_SZ / 8) * (F_SZ / 16) * 32];   // bf16x2 pairs
__device__ uint2  g_W2p[(P_SZ / 8) * (F_SZ / 16) * 32];
__device__ uint2  g_Fp [(F_SZ / 8) * (D_SZ / 16) * 32];   // fp16x2 pairs (features)
__device__ float  g_biasP[P_SZ];                          // -beta * pws[p]

__device__ __forceinline__ uint32_t smem_u32(const void* p) {
    uint32_t a;
    asm("{ .reg .u64 t; cvta.to.shared.u64 t, %1; cvt.u32.u64 %0, t; }" : "=r"(a) : "l"(p));
    return a;
}

// ===================== kernel 0: pack features into fp16 B-fragment layout =====================
__global__ __launch_bounds__(256)
void fpack_kernel(const float* __restrict__ features) {
    int idx = blockIdx.x * 256 + threadIdx.x;      // 64 nb * 16 kb * 32 lanes = 32768
    int lane = idx & 31;
    int kb   = (idx >> 5) & 15;
    int nb   = idx >> 9;
    int f = nb * 8 + (lane >> 2);
    int k = kb * 16 + (lane & 3) * 2;
    uint2 w;
#pragma unroll
    for (int r = 0; r < 2; r++) {
        float v0 = features[(size_t)f * D_SZ + k + r * 8];
        float v1 = features[(size_t)f * D_SZ + k + r * 8 + 1];
        __half2 h = __floats2half2_rn(v0, v1);
        uint32_t u = *reinterpret_cast<uint32_t*>(&h);
        if (r == 0) w.x = u; else w.y = u;
    }
    g_Fp[idx] = w;
}

// ===================== kernel 1: p-side precompute (tf32 wmma) + W pack =====================
__global__ __launch_bounds__(256, 1)
void pside_kernel(const float* __restrict__ prototypes,
                  const float* __restrict__ features,
                  const float* __restrict__ alpha,
                  const float* __restrict__ beta,
                  const float* __restrict__ theta) {
    extern __shared__ float smp[];
    float* ps   = smp;
    float* Outs = smp + 16 * PS_LD;

    int tid  = threadIdx.x;
    int warp = tid >> 5;
    int lane = tid & 31;
    int p0   = blockIdx.x * 16;

    {
        const float4* src = (const float4*)(prototypes + (size_t)p0 * D_SZ);
        for (int i = tid; i < 16 * D_SZ / 4; i += 256) {
            int row = i >> 6, q = i & 63;
            ((float4*)(ps + row * PS_LD))[q] = src[(size_t)row * 64 + q];
        }
    }
    __syncthreads();

    using FragA = wmma::fragment<wmma::matrix_a, 16, 16, 8, wmma::precision::tf32, wmma::row_major>;
    using FragB = wmma::fragment<wmma::matrix_b, 16, 16, 8, wmma::precision::tf32, wmma::col_major>;
    using FragC = wmma::fragment<wmma::accumulator, 16, 16, 8, float>;

    FragC c[4];
#pragma unroll
    for (int j = 0; j < 4; j++) wmma::fill_fragment(c[j], 0.f);

    int f0 = warp * 64;
#pragma unroll 4
    for (int k0 = 0; k0 < D_SZ; k0 += 8) {
        FragA a;
        wmma::load_matrix_sync(a, ps + k0, PS_LD);
#pragma unroll
        for (int e = 0; e < a.num_elements; e++) a.x[e] = wmma::__float_to_tf32(a.x[e]);
#pragma unroll
        for (int j = 0; j < 4; j++) {
            FragB b;
            wmma::load_matrix_sync(b, features + (size_t)(f0 + j * 16) * D_SZ + k0, D_SZ);
#pragma unroll
            for (int e = 0; e < b.num_elements; e++) b.x[e] = wmma::__float_to_tf32(b.x[e]);
            wmma::mma_sync(c[j], a, b, c[j]);
        }
    }
#pragma unroll
    for (int j = 0; j < 4; j++)
        wmma::store_matrix_sync(Outs + f0 + j * 16, c[j], F_SZ, wmma::mem_row_major);
    __syncthreads();

    float a_ = alpha[0], b_ = beta[0], th = theta[0];

    // pack W1/W2 fragments: CTA covers nb blocks {blockIdx*2, blockIdx*2+1}
    for (int idx = tid; idx < 2048; idx += 256) {
        int lanep = idx & 31;
        int kb    = (idx >> 5) & 31;
        int nbl   = idx >> 10;
        int pl = nbl * 8 + (lanep >> 2);
        int fb = kb * 16 + (lanep & 3) * 2;
        uint2 w1, w2;
#pragma unroll
        for (int r = 0; r < 2; r++) {
            float acc0 = Outs[pl * F_SZ + fb + r * 8];
            float acc1 = Outs[pl * F_SZ + fb + r * 8 + 1];
            float pp0 = fmaxf(acc0, 0.f), pp1 = fmaxf(acc1, 0.f);
            float pw0 = acc0 * pp0, pw1 = acc1 * pp1;
            __nv_bfloat162 v1 = __floats2bfloat162_rn(th * pw0 + a_ * pp0, th * pw1 + a_ * pp1);
            __nv_bfloat162 v2 = __floats2bfloat162_rn(b_ * pw0, b_ * pw1);
            uint32_t u1 = *reinterpret_cast<uint32_t*>(&v1);
            uint32_t u2 = *reinterpret_cast<uint32_t*>(&v2);
            if (r == 0) { w1.x = u1; w2.x = u2; } else { w1.y = u1; w2.y = u2; }
        }
        int nb = blockIdx.x * 2 + nbl;
        size_t off = ((size_t)nb * 32 + kb) * 32 + lanep;
        g_W1p[off] = w1;
        g_W2p[off] = w2;
    }

    for (int r = warp * 2; r < warp * 2 + 2; r++) {
        float s = 0.f;
        for (int cix = lane; cix < F_SZ; cix += 32) {
            float acc = Outs[r * F_SZ + cix];
            s += acc * fmaxf(acc, 0.f);
        }
#pragma unroll
        for (int o = 16; o > 0; o >>= 1) s += __shfl_xor_sync(0xffffffffu, s, o);
        if (lane == 0) g_biasP[p0 + r] = -b_ * s;
    }
}

// ===================== kernel 2: fused, 64-row CTAs, 2 CTA/SM, all raw mma.sync =====================
#define RS_BYTES   (64 * RS_LD * 2)                  // 66,560
#define BUF_OFF    RS_BYTES
#define BUF_BYTES  34048                             // xs only
#define RB_OFF     (BUF_OFF + BUF_BYTES)
#define BP_OFF     (RB_OFF + 256)
#define SMEM_FUSED (BP_OFF + 1024)                   // ≈ 99 KB

__global__ __launch_bounds__(256, 2)
void fused_kernel(const float* __restrict__ x,
                  const float* __restrict__ alpha,
                  float* __restrict__ out) {
    extern __shared__ char smraw[];
    __nv_bfloat16* Rs = (__nv_bfloat16*)smraw;
    float*         rb = (float*)(smraw + RB_OFF);
    float*         bp = (float*)(smraw + BP_OFF);

    int tid  = threadIdx.x;
    int warp = tid >> 5;
    int lane = tid & 31;
    int m0   = blockIdx.x * 64;

    const int r0   = lane >> 2;        // accumulator row within 8-block
    const int cofs = (lane & 3) * 2;   // accumulator col pair within 8-block
    const int mtx = lane >> 3, mrw = lane & 7;

    // ---------------- stage x tile as fp16 ----------------
    __half* xs = (__half*)(smraw + BUF_OFF);   // [64][XS_LD]
    {
        const float4* src = (const float4*)(x + (size_t)m0 * D_SZ);
        for (int i = tid; i < 64 * 64; i += 256) {
            int row = i >> 6, q = i & 63;
            float4 v = src[(size_t)row * 64 + q];
            __half2 h0 = __floats2half2_rn(v.x, v.y);
            __half2 h1 = __floats2half2_rn(v.z, v.w);
            uint2 w;
            w.x = *reinterpret_cast<uint32_t*>(&h0);
            w.y = *reinterpret_cast<uint32_t*>(&h1);
            *(uint2*)(xs + row * XS_LD + q * 4) = w;
        }
    }
    __syncthreads();

    // ---------------- Phase A: R = relu(x @ F^T), raw mma.sync f16, two f-passes ----------------
    const uint32_t su_xs = smem_u32(xs);
    const uint32_t xrow_off = (uint32_t)(((mtx & 1) * 8 + mrw) * (XS_LD * 2) + (mtx >> 1) * 16);

    for (int fpass = 0; fpass < 2; fpass++) {
        float c1[4][4][4];
#pragma unroll
        for (int i = 0; i < 4; i++)
#pragma unroll
            for (int j = 0; j < 4; j++)
#pragma unroll
                for (int e = 0; e < 4; e++) c1[i][j][e] = 0.f;

        int f0 = fpass * 256 + warp * 32;
        int nb0 = f0 >> 3;

#pragma unroll 4
        for (int kk = 0; kk < 16; kk++) {
            uint2 bf[4];
#pragma unroll
            for (int j = 0; j < 4; j++)
                bf[j] = g_Fp[((size_t)(nb0 + j) * 16 + kk) * 32 + lane];
#pragma unroll
            for (int i = 0; i < 4; i++) {
                uint32_t a0, a1, a2, a3;
                uint32_t addr = su_xs + (uint32_t)(i * 16 * XS_LD * 2 + kk * 32) + xrow_off;
                asm volatile("ldmatrix.sync.aligned.m8n8.x4.shared.b16 {%0,%1,%2,%3}, [%4];"
                             : "=r"(a0), "=r"(a1), "=r"(a2), "=r"(a3) : "r"(addr));
#pragma unroll
                for (int j = 0; j < 4; j++)
                    asm volatile("mma.sync.aligned.m16n8k16.row.col.f32.f16.f16.f32 "
                                 "{%0,%1,%2,%3}, {%4,%5,%6,%7}, {%8,%9}, {%0,%1,%2,%3};"
                                 : "+f"(c1[i][j][0]), "+f"(c1[i][j][1]),
                                   "+f"(c1[i][j][2]), "+f"(c1[i][j][3])
                                 : "r"(a0), "r"(a1), "r"(a2), "r"(a3),
                                   "r"(bf[j].x), "r"(bf[j].y));
            }
        }

        // direct epilogue: relu -> bf16x2 -> Rs (no staging)
#pragma unroll
        for (int i = 0; i < 4; i++)
#pragma unroll
            for (int j = 0; j < 4; j++) {
                int col = f0 + j * 8 + cofs;
                __nv_bfloat162 lo = __floats2bfloat162_rn(fmaxf(c1[i][j][0], 0.f), fmaxf(c1[i][j][1], 0.f));
                __nv_bfloat162 hi = __floats2bfloat162_rn(fmaxf(c1[i][j][2], 0.f), fmaxf(c1[i][j][3], 0.f));
                *reinterpret_cast<uint32_t*>(&Rs[(i * 16 + r0) * RS_LD + col])     = *reinterpret_cast<uint32_t*>(&lo);
                *reinterpret_cast<uint32_t*>(&Rs[(i * 16 + r0 + 8) * RS_LD + col]) = *reinterpret_cast<uint32_t*>(&hi);
            }
    }
    __syncthreads();   // Rs complete

    // row bias
    {
        float av = alpha[0];
        for (int r = warp * 8; r < warp * 8 + 8; r++) {
            float s = 0.f;
            for (int cix = lane; cix < F_SZ; cix += 32) {
                float v = __bfloat162float(Rs[r * RS_LD + cix]);
                s += v * v;
            }
#pragma unroll
            for (int o = 16; o > 0; o >>= 1) s += __shfl_xor_sync(0xffffffffu, s, o);
            if (lane == 0) rb[r] = -av * s;
        }
    }
    if (tid < P_SZ) bp[tid] = g_biasP[tid];

    // ---------------- Phase B: raw mma.sync bf16, 64x32 warp tiles ----------------
    float c2[4][4][4];
#pragma unroll
    for (int i = 0; i < 4; i++)
#pragma unroll
        for (int j = 0; j < 4; j++)
#pragma unroll
            for (int e = 0; e < 4; e++) c2[i][j][e] = 0.f;

    const uint32_t su_rs = smem_u32(Rs);
    const uint32_t arow_off = (uint32_t)(((mtx & 1) * 8 + mrw) * (RS_LD * 2) + (mtx >> 1) * 16);

#pragma unroll 4
    for (int kk = 0; kk < 32; kk++) {
        uint2 b1r[4], b2r[4];
#pragma unroll
        for (int j = 0; j < 4; j++) {
            size_t off = ((size_t)(warp * 4 + j) * 32 + kk) * 32 + lane;
            b1r[j] = g_W1p[off];
            b2r[j] = g_W2p[off];
        }
#pragma unroll
        for (int i = 0; i < 4; i++) {
            uint32_t a0, a1, a2, a3;
            uint32_t addr = su_rs + (uint32_t)(i * 16 * RS_LD * 2 + kk * 32) + arow_off;
            asm volatile("ldmatrix.sync.aligned.m8n8.x4.shared.b16 {%0,%1,%2,%3}, [%4];"
                         : "=r"(a0), "=r"(a1), "=r"(a2), "=r"(a3) : "r"(addr));
#pragma unroll
            for (int j = 0; j < 4; j++)
                asm volatile("mma.sync.aligned.m16n8k16.row.col.f32.bf16.bf16.f32 "
                             "{%0,%1,%2,%3}, {%4,%5,%6,%7}, {%8,%9}, {%0,%1,%2,%3};"
                             : "+f"(c2[i][j][0]), "+f"(c2[i][j][1]),
                               "+f"(c2[i][j][2]), "+f"(c2[i][j][3])
                             : "r"(a0), "r"(a1), "r"(a2), "r"(a3),
                               "r"(b2r[j].x), "r"(b2r[j].y));
            {
                __nv_bfloat162* p0 = reinterpret_cast<__nv_bfloat162*>(&a0);
                __nv_bfloat162* p1 = reinterpret_cast<__nv_bfloat162*>(&a1);
                __nv_bfloat162* p2 = reinterpret_cast<__nv_bfloat162*>(&a2);
                __nv_bfloat162* p3 = reinterpret_cast<__nv_bfloat162*>(&a3);
                *p0 = __hmul2(*p0, *p0); *p1 = __hmul2(*p1, *p1);
                *p2 = __hmul2(*p2, *p2); *p3 = __hmul2(*p3, *p3);
            }
#pragma unroll
            for (int j = 0; j < 4; j++)
                asm volatile("mma.sync.aligned.m16n8k16.row.col.f32.bf16.bf16.f32 "
                             "{%0,%1,%2,%3}, {%4,%5,%6,%7}, {%8,%9}, {%0,%1,%2,%3};"
                             : "+f"(c2[i][j][0]), "+f"(c2[i][j][1]),
                               "+f"(c2[i][j][2]), "+f"(c2[i][j][3])
                             : "r"(a0), "r"(a1), "r"(a2), "r"(a3),
                               "r"(b1r[j].x), "r"(b1r[j].y));
        }
    }
    __syncthreads();   // Rs dead -> Os takes over

    float* Os = (float*)smraw;
    {
        int ncol = warp * 32;
#pragma unroll
        for (int i = 0; i < 4; i++)
#pragma unroll
            for (int j = 0; j < 4; j++) {
                int col = ncol + j * 8 + cofs;
                *(float2*)(Os + (i * 16 + r0) * OS_LD + col)     = make_float2(c2[i][j][0], c2[i][j][1]);
                *(float2*)(Os + (i * 16 + r0 + 8) * OS_LD + col) = make_float2(c2[i][j][2], c2[i][j][3]);
            }
    }
    __syncthreads();

    for (int i = tid; i < 64 * P_SZ; i += 256) {
        int r = i >> 8;
        int p = i & 255;
        out[(size_t)(m0 + r) * P_SZ + p] = Os[r * OS_LD + p] + rb[r] + bp[p];
    }
}

// =========================== launch ===========================
extern "C" void kernel_launch(void* const* d_in, const int* in_sizes, int n_in,
                              void* d_out, int out_size) {
    const float* x          = (const float*)d_in[0];
    const float* features   = (const float*)d_in[1];
    const float* prototypes = (const float*)d_in[2];
    const float* alpha      = (const float*)d_in[3];
    const float* beta       = (const float*)d_in[4];
    const float* theta      = (const float*)d_in[5];
    float* out = (float*)d_out;

    cudaFuncSetAttribute(pside_kernel, cudaFuncAttributeMaxDynamicSharedMemorySize, 64 * 1024);
    cudaFuncSetAttribute(fused_kernel, cudaFuncAttributeMaxDynamicSharedMemorySize, SMEM_FUSED);

    fpack_kernel<<<(F_SZ / 8) * (D_SZ / 16) * 32 / 256, 256>>>(features);
    pside_kernel<<<P_SZ / 16, 256, 64 * 1024>>>(prototypes, features, alpha, beta, theta);
    fused_kernel<<<B_SZ / 64, 256, SMEM_FUSED>>>(x, alpha, out);
}

// round 14
// speedup vs baseline: 1.4599x; 1.4599x over previous
#include <cuda_runtime.h>
#include <cuda_bf16.h>
#include <cuda_fp16.h>
#include <mma.h>
#include <cstdint>

using namespace nvcuda;

#define B_SZ 65536
#define D_SZ 256
#define F_SZ 512
#define P_SZ 256

// padded smem strides — all row strides odd in 16B units => conflict-free
#define RS_LD  520   // bf16: 1040B = 65 units
#define XS_LD  264   // fp16: 528B  = 33 units
#define OS_LD  260   // fp32: 1040B = 65 units
#define PS_LD  260   // pside fp32

// ---------------- scratch (static device globals; no allocations) ----------------
// Packed B-fragment layout for mma.sync m16n8k16 (row.col):
//   [nb][kb][lane] -> uint2 ; reg r of lane l holds  M[n = nb*8 + l/4][k = kb*16 + (l%4)*2 + 8r .. +1]
__device__ uint2  g_W1p[(P_SZ / 8) * (F_SZ / 16) * 32];   // bf16x2 pairs
__device__ uint2  g_W2p[(P_SZ / 8) * (F_SZ / 16) * 32];
__device__ uint2  g_Fp [(F_SZ / 8) * (D_SZ / 16) * 32];   // fp16x2 pairs (features)
__device__ float  g_biasP[P_SZ];                          // -beta * pws[p]

__device__ __forceinline__ uint32_t smem_u32(const void* p) {
    uint32_t a;
    asm("{ .reg .u64 t; cvta.to.shared.u64 t, %1; cvt.u32.u64 %0, t; }" : "=r"(a) : "l"(p));
    return a;
}

// ===================== kernel 0: pack features into fp16 B-fragment layout =====================
__global__ __launch_bounds__(256)
void fpack_kernel(const float* __restrict__ features) {
    int idx = blockIdx.x * 256 + threadIdx.x;      // 64 nb * 16 kb * 32 lanes = 32768
    int lane = idx & 31;
    int kb   = (idx >> 5) & 15;
    int nb   = idx >> 9;
    int f = nb * 8 + (lane >> 2);
    int k = kb * 16 + (lane & 3) * 2;
    uint2 w;
#pragma unroll
    for (int r = 0; r < 2; r++) {
        float v0 = features[(size_t)f * D_SZ + k + r * 8];
        float v1 = features[(size_t)f * D_SZ + k + r * 8 + 1];
        __half2 h = __floats2half2_rn(v0, v1);
        uint32_t u = *reinterpret_cast<uint32_t*>(&h);
        if (r == 0) w.x = u; else w.y = u;
    }
    g_Fp[idx] = w;
}

// ===================== kernel 1: p-side precompute (tf32 wmma) + W pack =====================
__global__ __launch_bounds__(256, 1)
void pside_kernel(const float* __restrict__ prototypes,
                  const float* __restrict__ features,
                  const float* __restrict__ alpha,
                  const float* __restrict__ beta,
                  const float* __restrict__ theta) {
    extern __shared__ float smp[];
    float* ps   = smp;
    float* Outs = smp + 16 * PS_LD;

    int tid  = threadIdx.x;
    int warp = tid >> 5;
    int lane = tid & 31;
    int p0   = blockIdx.x * 16;

    {
        const float4* src = (const float4*)(prototypes + (size_t)p0 * D_SZ);
        for (int i = tid; i < 16 * D_SZ / 4; i += 256) {
            int row = i >> 6, q = i & 63;
            ((float4*)(ps + row * PS_LD))[q] = src[(size_t)row * 64 + q];
        }
    }
    __syncthreads();

    using FragA = wmma::fragment<wmma::matrix_a, 16, 16, 8, wmma::precision::tf32, wmma::row_major>;
    using FragB = wmma::fragment<wmma::matrix_b, 16, 16, 8, wmma::precision::tf32, wmma::col_major>;
    using FragC = wmma::fragment<wmma::accumulator, 16, 16, 8, float>;

    FragC c[4];
#pragma unroll
    for (int j = 0; j < 4; j++) wmma::fill_fragment(c[j], 0.f);

    int f0 = warp * 64;
#pragma unroll 4
    for (int k0 = 0; k0 < D_SZ; k0 += 8) {
        FragA a;
        wmma::load_matrix_sync(a, ps + k0, PS_LD);
#pragma unroll
        for (int e = 0; e < a.num_elements; e++) a.x[e] = wmma::__float_to_tf32(a.x[e]);
#pragma unroll
        for (int j = 0; j < 4; j++) {
            FragB b;
            wmma::load_matrix_sync(b, features + (size_t)(f0 + j * 16) * D_SZ + k0, D_SZ);
#pragma unroll
            for (int e = 0; e < b.num_elements; e++) b.x[e] = wmma::__float_to_tf32(b.x[e]);
            wmma::mma_sync(c[j], a, b, c[j]);
        }
    }
#pragma unroll
    for (int j = 0; j < 4; j++)
        wmma::store_matrix_sync(Outs + f0 + j * 16, c[j], F_SZ, wmma::mem_row_major);
    __syncthreads();

    float a_ = alpha[0], b_ = beta[0], th = theta[0];

    // pack W1/W2 fragments: CTA covers nb blocks {blockIdx*2, blockIdx*2+1}
    for (int idx = tid; idx < 2048; idx += 256) {
        int lanep = idx & 31;
        int kb    = (idx >> 5) & 31;
        int nbl   = idx >> 10;
        int pl = nbl * 8 + (lanep >> 2);
        int fb = kb * 16 + (lanep & 3) * 2;
        uint2 w1, w2;
#pragma unroll
        for (int r = 0; r < 2; r++) {
            float acc0 = Outs[pl * F_SZ + fb + r * 8];
            float acc1 = Outs[pl * F_SZ + fb + r * 8 + 1];
            float pp0 = fmaxf(acc0, 0.f), pp1 = fmaxf(acc1, 0.f);
            float pw0 = acc0 * pp0, pw1 = acc1 * pp1;
            __nv_bfloat162 v1 = __floats2bfloat162_rn(th * pw0 + a_ * pp0, th * pw1 + a_ * pp1);
            __nv_bfloat162 v2 = __floats2bfloat162_rn(b_ * pw0, b_ * pw1);
            uint32_t u1 = *reinterpret_cast<uint32_t*>(&v1);
            uint32_t u2 = *reinterpret_cast<uint32_t*>(&v2);
            if (r == 0) { w1.x = u1; w2.x = u2; } else { w1.y = u1; w2.y = u2; }
        }
        int nb = blockIdx.x * 2 + nbl;
        size_t off = ((size_t)nb * 32 + kb) * 32 + lanep;
        g_W1p[off] = w1;
        g_W2p[off] = w2;
    }

    for (int r = warp * 2; r < warp * 2 + 2; r++) {
        float s = 0.f;
        for (int cix = lane; cix < F_SZ; cix += 32) {
            float acc = Outs[r * F_SZ + cix];
            s += acc * fmaxf(acc, 0.f);
        }
#pragma unroll
        for (int o = 16; o > 0; o >>= 1) s += __shfl_xor_sync(0xffffffffu, s, o);
        if (lane == 0) g_biasP[p0 + r] = -b_ * s;
    }
}

// ===================== kernel 2: fused, 64-row CTAs, 2 CTA/SM, raw mma.sync + prefetch =====================
#define RS_BYTES   (64 * RS_LD * 2)                  // 66,560
#define BUF_OFF    RS_BYTES
#define BUF_BYTES  34048                             // xs only
#define RB_OFF     (BUF_OFF + BUF_BYTES)
#define BP_OFF     (RB_OFF + 256)
#define SMEM_FUSED (BP_OFF + 1024)                   // ≈ 99 KB

__global__ __launch_bounds__(256, 2)
void fused_kernel(const float* __restrict__ x,
                  const float* __restrict__ alpha,
                  float* __restrict__ out) {
    extern __shared__ char smraw[];
    __nv_bfloat16* Rs = (__nv_bfloat16*)smraw;
    float*         rb = (float*)(smraw + RB_OFF);
    float*         bp = (float*)(smraw + BP_OFF);

    int tid  = threadIdx.x;
    int warp = tid >> 5;
    int lane = tid & 31;
    int m0   = blockIdx.x * 64;

    const int r0   = lane >> 2;
    const int cofs = (lane & 3) * 2;
    const int mtx = lane >> 3, mrw = lane & 7;

    // ---------------- stage x tile as fp16 ----------------
    __half* xs = (__half*)(smraw + BUF_OFF);   // [64][XS_LD]
    {
        const float4* src = (const float4*)(x + (size_t)m0 * D_SZ);
        for (int i = tid; i < 64 * 64; i += 256) {
            int row = i >> 6, q = i & 63;
            float4 v = src[(size_t)row * 64 + q];
            __half2 h0 = __floats2half2_rn(v.x, v.y);
            __half2 h1 = __floats2half2_rn(v.z, v.w);
            uint2 w;
            w.x = *reinterpret_cast<uint32_t*>(&h0);
            w.y = *reinterpret_cast<uint32_t*>(&h1);
            *(uint2*)(xs + row * XS_LD + q * 4) = w;
        }
    }
    __syncthreads();

    // ---------------- Phase A: R = relu(x @ F^T), raw mma.sync f16, B prefetched ----------------
    const uint32_t su_xs = smem_u32(xs);
    const uint32_t xrow_off = (uint32_t)(((mtx & 1) * 8 + mrw) * (XS_LD * 2) + (mtx >> 1) * 16);

    for (int fpass = 0; fpass < 2; fpass++) {
        float c1[4][4][4];
#pragma unroll
        for (int i = 0; i < 4; i++)
#pragma unroll
            for (int j = 0; j < 4; j++)
#pragma unroll
                for (int e = 0; e < 4; e++) c1[i][j][e] = 0.f;

        int f0 = fpass * 256 + warp * 32;
        int nb0 = f0 >> 3;

        uint2 bf[2][4];   // [buf][j]
#pragma unroll
        for (int j = 0; j < 4; j++)
            bf[0][j] = g_Fp[((size_t)(nb0 + j) * 16) * 32 + lane];

#pragma unroll 8
        for (int kk = 0; kk < 16; kk++) {
            int cur = kk & 1, nxt = cur ^ 1;
            if (kk < 15) {
#pragma unroll
                for (int j = 0; j < 4; j++)
                    bf[nxt][j] = g_Fp[((size_t)(nb0 + j) * 16 + kk + 1) * 32 + lane];
            }
#pragma unroll
            for (int i = 0; i < 4; i++) {
                uint32_t a0, a1, a2, a3;
                uint32_t addr = su_xs + (uint32_t)(i * 16 * XS_LD * 2 + kk * 32) + xrow_off;
                asm volatile("ldmatrix.sync.aligned.m8n8.x4.shared.b16 {%0,%1,%2,%3}, [%4];"
                             : "=r"(a0), "=r"(a1), "=r"(a2), "=r"(a3) : "r"(addr));
#pragma unroll
                for (int j = 0; j < 4; j++)
                    asm volatile("mma.sync.aligned.m16n8k16.row.col.f32.f16.f16.f32 "
                                 "{%0,%1,%2,%3}, {%4,%5,%6,%7}, {%8,%9}, {%0,%1,%2,%3};"
                                 : "+f"(c1[i][j][0]), "+f"(c1[i][j][1]),
                                   "+f"(c1[i][j][2]), "+f"(c1[i][j][3])
                                 : "r"(a0), "r"(a1), "r"(a2), "r"(a3),
                                   "r"(bf[cur][j].x), "r"(bf[cur][j].y));
            }
        }

        // direct epilogue: relu -> bf16x2 -> Rs
#pragma unroll
        for (int i = 0; i < 4; i++)
#pragma unroll
            for (int j = 0; j < 4; j++) {
                int col = f0 + j * 8 + cofs;
                __nv_bfloat162 lo = __floats2bfloat162_rn(fmaxf(c1[i][j][0], 0.f), fmaxf(c1[i][j][1], 0.f));
                __nv_bfloat162 hi = __floats2bfloat162_rn(fmaxf(c1[i][j][2], 0.f), fmaxf(c1[i][j][3], 0.f));
                *reinterpret_cast<uint32_t*>(&Rs[(i * 16 + r0) * RS_LD + col])     = *reinterpret_cast<uint32_t*>(&lo);
                *reinterpret_cast<uint32_t*>(&Rs[(i * 16 + r0 + 8) * RS_LD + col]) = *reinterpret_cast<uint32_t*>(&hi);
            }
    }
    __syncthreads();   // Rs complete

    // row bias
    {
        float av = alpha[0];
        for (int r = warp * 8; r < warp * 8 + 8; r++) {
            float s = 0.f;
            for (int cix = lane; cix < F_SZ; cix += 32) {
                float v = __bfloat162float(Rs[r * RS_LD + cix]);
                s += v * v;
            }
#pragma unroll
            for (int o = 16; o > 0; o >>= 1) s += __shfl_xor_sync(0xffffffffu, s, o);
            if (lane == 0) rb[r] = -av * s;
        }
    }
    if (tid < P_SZ) bp[tid] = g_biasP[tid];

    // ---------------- Phase B: raw mma.sync bf16, 64x32 warp tiles, B prefetched ----------------
    float c2[4][4][4];
#pragma unroll
    for (int i = 0; i < 4; i++)
#pragma unroll
        for (int j = 0; j < 4; j++)
#pragma unroll
            for (int e = 0; e < 4; e++) c2[i][j][e] = 0.f;

    const uint32_t su_rs = smem_u32(Rs);
    const uint32_t arow_off = (uint32_t)(((mtx & 1) * 8 + mrw) * (RS_LD * 2) + (mtx >> 1) * 16);

    uint2 b1r[2][4], b2r[2][4];   // [buf][j]
#pragma unroll
    for (int j = 0; j < 4; j++) {
        size_t off = ((size_t)(warp * 4 + j) * 32) * 32 + lane;
        b1r[0][j] = g_W1p[off];
        b2r[0][j] = g_W2p[off];
    }

#pragma unroll 8
    for (int kk = 0; kk < 32; kk++) {
        int cur = kk & 1, nxt = cur ^ 1;
        if (kk < 31) {
#pragma unroll
            for (int j = 0; j < 4; j++) {
                size_t off = ((size_t)(warp * 4 + j) * 32 + kk + 1) * 32 + lane;
                b1r[nxt][j] = g_W1p[off];
                b2r[nxt][j] = g_W2p[off];
            }
        }
#pragma unroll
        for (int i = 0; i < 4; i++) {
            uint32_t a0, a1, a2, a3;
            uint32_t addr = su_rs + (uint32_t)(i * 16 * RS_LD * 2 + kk * 32) + arow_off;
            asm volatile("ldmatrix.sync.aligned.m8n8.x4.shared.b16 {%0,%1,%2,%3}, [%4];"
                         : "=r"(a0), "=r"(a1), "=r"(a2), "=r"(a3) : "r"(addr));
#pragma unroll
            for (int j = 0; j < 4; j++)
                asm volatile("mma.sync.aligned.m16n8k16.row.col.f32.bf16.bf16.f32 "
                             "{%0,%1,%2,%3}, {%4,%5,%6,%7}, {%8,%9}, {%0,%1,%2,%3};"
                             : "+f"(c2[i][j][0]), "+f"(c2[i][j][1]),
                               "+f"(c2[i][j][2]), "+f"(c2[i][j][3])
                             : "r"(a0), "r"(a1), "r"(a2), "r"(a3),
                               "r"(b2r[cur][j].x), "r"(b2r[cur][j].y));
            {
                __nv_bfloat162* p0 = reinterpret_cast<__nv_bfloat162*>(&a0);
                __nv_bfloat162* p1 = reinterpret_cast<__nv_bfloat162*>(&a1);
                __nv_bfloat162* p2 = reinterpret_cast<__nv_bfloat162*>(&a2);
                __nv_bfloat162* p3 = reinterpret_cast<__nv_bfloat162*>(&a3);
                *p0 = __hmul2(*p0, *p0); *p1 = __hmul2(*p1, *p1);
                *p2 = __hmul2(*p2, *p2); *p3 = __hmul2(*p3, *p3);
            }
#pragma unroll
            for (int j = 0; j < 4; j++)
                asm volatile("mma.sync.aligned.m16n8k16.row.col.f32.bf16.bf16.f32 "
                             "{%0,%1,%2,%3}, {%4,%5,%6,%7}, {%8,%9}, {%0,%1,%2,%3};"
                             : "+f"(c2[i][j][0]), "+f"(c2[i][j][1]),
                               "+f"(c2[i][j][2]), "+f"(c2[i][j][3])
                             : "r"(a0), "r"(a1), "r"(a2), "r"(a3),
                               "r"(b1r[cur][j].x), "r"(b1r[cur][j].y));
        }
    }
    __syncthreads();   // Rs dead -> Os takes over

    float* Os = (float*)smraw;
    {
        int ncol = warp * 32;
#pragma unroll
        for (int i = 0; i < 4; i++)
#pragma unroll
            for (int j = 0; j < 4; j++) {
                int col = ncol + j * 8 + cofs;
                *(float2*)(Os + (i * 16 + r0) * OS_LD + col)     = make_float2(c2[i][j][0], c2[i][j][1]);
                *(float2*)(Os + (i * 16 + r0 + 8) * OS_LD + col) = make_float2(c2[i][j][2], c2[i][j][3]);
            }
    }
    __syncthreads();

    for (int i = tid; i < 64 * P_SZ; i += 256) {
        int r = i >> 8;
        int p = i & 255;
        out[(size_t)(m0 + r) * P_SZ + p] = Os[r * OS_LD + p] + rb[r] + bp[p];
    }
}

// =========================== launch ===========================
extern "C" void kernel_launch(void* const* d_in, const int* in_sizes, int n_in,
                              void* d_out, int out_size) {
    const float* x          = (const float*)d_in[0];
    const float* features   = (const float*)d_in[1];
    const float* prototypes = (const float*)d_in[2];
    const float* alpha      = (const float*)d_in[3];
    const float* beta       = (const float*)d_in[4];
    const float* theta      = (const float*)d_in[5];
    float* out = (float*)d_out;

    cudaFuncSetAttribute(pside_kernel, cudaFuncAttributeMaxDynamicSharedMemorySize, 64 * 1024);
    cudaFuncSetAttribute(fused_kernel, cudaFuncAttributeMaxDynamicSharedMemorySize, SMEM_FUSED);

    fpack_kernel<<<(F_SZ / 8) * (D_SZ / 16) * 32 / 256, 256>>>(features);
    pside_kernel<<<P_SZ / 16, 256, 64 * 1024>>>(prototypes, features, alpha, beta, theta);
    fused_kernel<<<B_SZ / 64, 256, SMEM_FUSED>>>(x, alpha, out);
}

// round 15
// speedup vs baseline: 1.6403x; 1.1236x over previous
#include <cuda_runtime.h>
#include <cuda_bf16.h>
#include <cuda_fp16.h>
#include <mma.h>
#include <cstdint>

using namespace nvcuda;

#define B_SZ 65536
#define D_SZ 256
#define F_SZ 512
#define P_SZ 256

// padded smem strides — all row strides odd in 16B units => conflict-free
#define RS_LD  520   // bf16: 1040B = 65 units
#define XS_LD  264   // fp16: 528B  = 33 units
#define PS_LD  260   // pside fp32

// ---------------- scratch (static device globals; no allocations) ----------------
// Packed B-fragment layout for mma.sync m16n8k16 (row.col):
//   [nb][kb][lane] -> uint2 ; reg r of lane l holds  M[n = nb*8 + l/4][k = kb*16 + (l%4)*2 + 8r .. +1]
__device__ uint2  g_W1p[(P_SZ / 8) * (F_SZ / 16) * 32];   // bf16x2 pairs
__device__ uint2  g_W2p[(P_SZ / 8) * (F_SZ / 16) * 32];
__device__ uint2  g_Fp [(F_SZ / 8) * (D_SZ / 16) * 32];   // fp16x2 pairs (features)
__device__ float  g_biasP[P_SZ];                          // -beta * pws[p]

__device__ __forceinline__ uint32_t smem_u32(const void* p) {
    uint32_t a;
    asm("{ .reg .u64 t; cvta.to.shared.u64 t, %1; cvt.u32.u64 %0, t; }" : "=r"(a) : "l"(p));
    return a;
}

// ===================== kernel 1: heterogeneous prep =====================
// blocks 0..15: p-side precompute (tf32 wmma) + W pack; blocks 16..143: features pack.
__global__ __launch_bounds__(256, 1)
void prep_kernel(const float* __restrict__ prototypes,
                 const float* __restrict__ features,
                 const float* __restrict__ alpha,
                 const float* __restrict__ beta,
                 const float* __restrict__ theta) {
    int tid  = threadIdx.x;

    if (blockIdx.x >= 16) {
        // ---- fpack role ----
        int idx = (blockIdx.x - 16) * 256 + tid;      // 64 nb * 16 kb * 32 lanes = 32768
        int lane = idx & 31;
        int kb   = (idx >> 5) & 15;
        int nb   = idx >> 9;
        int f = nb * 8 + (lane >> 2);
        int k = kb * 16 + (lane & 3) * 2;
        uint2 w;
#pragma unroll
        for (int r = 0; r < 2; r++) {
            float v0 = features[(size_t)f * D_SZ + k + r * 8];
            float v1 = features[(size_t)f * D_SZ + k + r * 8 + 1];
            __half2 h = __floats2half2_rn(v0, v1);
            uint32_t u = *reinterpret_cast<uint32_t*>(&h);
            if (r == 0) w.x = u; else w.y = u;
        }
        g_Fp[idx] = w;
        return;
    }

    // ---- pside role ----
    extern __shared__ float smp[];
    float* ps   = smp;
    float* Outs = smp + 16 * PS_LD;

    int warp = tid >> 5;
    int lane = tid & 31;
    int p0   = blockIdx.x * 16;

    {
        const float4* src = (const float4*)(prototypes + (size_t)p0 * D_SZ);
        for (int i = tid; i < 16 * D_SZ / 4; i += 256) {
            int row = i >> 6, q = i & 63;
            ((float4*)(ps + row * PS_LD))[q] = src[(size_t)row * 64 + q];
        }
    }
    __syncthreads();

    using FragA = wmma::fragment<wmma::matrix_a, 16, 16, 8, wmma::precision::tf32, wmma::row_major>;
    using FragB = wmma::fragment<wmma::matrix_b, 16, 16, 8, wmma::precision::tf32, wmma::col_major>;
    using FragC = wmma::fragment<wmma::accumulator, 16, 16, 8, float>;

    FragC c[4];
#pragma unroll
    for (int j = 0; j < 4; j++) wmma::fill_fragment(c[j], 0.f);

    int f0 = warp * 64;
#pragma unroll 4
    for (int k0 = 0; k0 < D_SZ; k0 += 8) {
        FragA a;
        wmma::load_matrix_sync(a, ps + k0, PS_LD);
#pragma unroll
        for (int e = 0; e < a.num_elements; e++) a.x[e] = wmma::__float_to_tf32(a.x[e]);
#pragma unroll
        for (int j = 0; j < 4; j++) {
            FragB b;
            wmma::load_matrix_sync(b, features + (size_t)(f0 + j * 16) * D_SZ + k0, D_SZ);
#pragma unroll
            for (int e = 0; e < b.num_elements; e++) b.x[e] = wmma::__float_to_tf32(b.x[e]);
            wmma::mma_sync(c[j], a, b, c[j]);
        }
    }
#pragma unroll
    for (int j = 0; j < 4; j++)
        wmma::store_matrix_sync(Outs + f0 + j * 16, c[j], F_SZ, wmma::mem_row_major);
    __syncthreads();

    float a_ = alpha[0], b_ = beta[0], th = theta[0];

    // pack W1/W2 fragments: CTA covers nb blocks {blockIdx*2, blockIdx*2+1}
    for (int idx = tid; idx < 2048; idx += 256) {
        int lanep = idx & 31;
        int kb    = (idx >> 5) & 31;
        int nbl   = idx >> 10;
        int pl = nbl * 8 + (lanep >> 2);
        int fb = kb * 16 + (lanep & 3) * 2;
        uint2 w1, w2;
#pragma unroll
        for (int r = 0; r < 2; r++) {
            float acc0 = Outs[pl * F_SZ + fb + r * 8];
            float acc1 = Outs[pl * F_SZ + fb + r * 8 + 1];
            float pp0 = fmaxf(acc0, 0.f), pp1 = fmaxf(acc1, 0.f);
            float pw0 = acc0 * pp0, pw1 = acc1 * pp1;
            __nv_bfloat162 v1 = __floats2bfloat162_rn(th * pw0 + a_ * pp0, th * pw1 + a_ * pp1);
            __nv_bfloat162 v2 = __floats2bfloat162_rn(b_ * pw0, b_ * pw1);
            uint32_t u1 = *reinterpret_cast<uint32_t*>(&v1);
            uint32_t u2 = *reinterpret_cast<uint32_t*>(&v2);
            if (r == 0) { w1.x = u1; w2.x = u2; } else { w1.y = u1; w2.y = u2; }
        }
        int nb = blockIdx.x * 2 + nbl;
        size_t off = ((size_t)nb * 32 + kb) * 32 + lanep;
        g_W1p[off] = w1;
        g_W2p[off] = w2;
    }

    for (int r = warp * 2; r < warp * 2 + 2; r++) {
        float s = 0.f;
        for (int cix = lane; cix < F_SZ; cix += 32) {
            float acc = Outs[r * F_SZ + cix];
            s += acc * fmaxf(acc, 0.f);
        }
#pragma unroll
        for (int o = 16; o > 0; o >>= 1) s += __shfl_xor_sync(0xffffffffu, s, o);
        if (lane == 0) g_biasP[p0 + r] = -b_ * s;
    }
}

// ===================== kernel 2: fused, 64-row CTAs, 2 CTA/SM =====================
#define RS_BYTES   (64 * RS_LD * 2)                  // 66,560
#define BUF_OFF    RS_BYTES
#define BUF_BYTES  34048                             // xs
#define RB_OFF     (BUF_OFF + BUF_BYTES)
#define BP_OFF     (RB_OFF + 256)
#define RBP_OFF    (BP_OFF + 1024)                   // rbpart fp32[8][64]
#define SMEM_FUSED (RBP_OFF + 2048)                  // ≈ 102 KB

__global__ __launch_bounds__(256, 2)
void fused_kernel(const float* __restrict__ x,
                  const float* __restrict__ alpha,
                  float* __restrict__ out) {
    extern __shared__ char smraw[];
    __nv_bfloat16* Rs     = (__nv_bfloat16*)smraw;
    float*         rb     = (float*)(smraw + RB_OFF);
    float*         bp     = (float*)(smraw + BP_OFF);
    float*         rbpart = (float*)(smraw + RBP_OFF);

    int tid  = threadIdx.x;
    int warp = tid >> 5;
    int lane = tid & 31;
    int m0   = blockIdx.x * 64;

    const int r0   = lane >> 2;
    const int cofs = (lane & 3) * 2;
    const int mtx = lane >> 3, mrw = lane & 7;

    // ---------------- stage x tile as fp16 ----------------
    __half* xs = (__half*)(smraw + BUF_OFF);   // [64][XS_LD]
    {
        const float4* src = (const float4*)(x + (size_t)m0 * D_SZ);
        for (int i = tid; i < 64 * 64; i += 256) {
            int row = i >> 6, q = i & 63;
            float4 v = src[(size_t)row * 64 + q];
            __half2 h0 = __floats2half2_rn(v.x, v.y);
            __half2 h1 = __floats2half2_rn(v.z, v.w);
            uint2 w;
            w.x = *reinterpret_cast<uint32_t*>(&h0);
            w.y = *reinterpret_cast<uint32_t*>(&h1);
            *(uint2*)(xs + row * XS_LD + q * 4) = w;
        }
    }
    __syncthreads();

    // ---------------- Phase A: R = relu(x @ F^T), raw mma.sync f16, B prefetched ----------------
    const uint32_t su_xs = smem_u32(xs);
    const uint32_t xrow_off = (uint32_t)(((mtx & 1) * 8 + mrw) * (XS_LD * 2) + (mtx >> 1) * 16);

    float rs[8];    // row-sum partials: [i*2] -> row i*16+r0 ; [i*2+1] -> row i*16+r0+8
#pragma unroll
    for (int e = 0; e < 8; e++) rs[e] = 0.f;

    for (int fpass = 0; fpass < 2; fpass++) {
        float c1[4][4][4];
#pragma unroll
        for (int i = 0; i < 4; i++)
#pragma unroll
            for (int j = 0; j < 4; j++)
#pragma unroll
                for (int e = 0; e < 4; e++) c1[i][j][e] = 0.f;

        int f0 = fpass * 256 + warp * 32;
        int nb0 = f0 >> 3;

        uint2 bf[2][4];
#pragma unroll
        for (int j = 0; j < 4; j++)
            bf[0][j] = g_Fp[((size_t)(nb0 + j) * 16) * 32 + lane];

#pragma unroll 8
        for (int kk = 0; kk < 16; kk++) {
            int cur = kk & 1, nxt = cur ^ 1;
            if (kk < 15) {
#pragma unroll
                for (int j = 0; j < 4; j++)
                    bf[nxt][j] = g_Fp[((size_t)(nb0 + j) * 16 + kk + 1) * 32 + lane];
            }
#pragma unroll
            for (int i = 0; i < 4; i++) {
                uint32_t a0, a1, a2, a3;
                uint32_t addr = su_xs + (uint32_t)(i * 16 * XS_LD * 2 + kk * 32) + xrow_off;
                asm volatile("ldmatrix.sync.aligned.m8n8.x4.shared.b16 {%0,%1,%2,%3}, [%4];"
                             : "=r"(a0), "=r"(a1), "=r"(a2), "=r"(a3) : "r"(addr));
#pragma unroll
                for (int j = 0; j < 4; j++)
                    asm volatile("mma.sync.aligned.m16n8k16.row.col.f32.f16.f16.f32 "
                                 "{%0,%1,%2,%3}, {%4,%5,%6,%7}, {%8,%9}, {%0,%1,%2,%3};"
                                 : "+f"(c1[i][j][0]), "+f"(c1[i][j][1]),
                                   "+f"(c1[i][j][2]), "+f"(c1[i][j][3])
                                 : "r"(a0), "r"(a1), "r"(a2), "r"(a3),
                                   "r"(bf[cur][j].x), "r"(bf[cur][j].y));
            }
        }

        // direct epilogue: relu (fp32) -> row-sum partials + bf16x2 -> Rs
#pragma unroll
        for (int i = 0; i < 4; i++)
#pragma unroll
            for (int j = 0; j < 4; j++) {
                int col = f0 + j * 8 + cofs;
                float v0 = fmaxf(c1[i][j][0], 0.f), v1 = fmaxf(c1[i][j][1], 0.f);
                float v2 = fmaxf(c1[i][j][2], 0.f), v3 = fmaxf(c1[i][j][3], 0.f);
                rs[i * 2]     += v0 * v0 + v1 * v1;
                rs[i * 2 + 1] += v2 * v2 + v3 * v3;
                __nv_bfloat162 lo = __floats2bfloat162_rn(v0, v1);
                __nv_bfloat162 hi = __floats2bfloat162_rn(v2, v3);
                *reinterpret_cast<uint32_t*>(&Rs[(i * 16 + r0) * RS_LD + col])     = *reinterpret_cast<uint32_t*>(&lo);
                *reinterpret_cast<uint32_t*>(&Rs[(i * 16 + r0 + 8) * RS_LD + col]) = *reinterpret_cast<uint32_t*>(&hi);
            }
    }

    // reduce row-sums across the 4 lanes of each row quad, stash per-warp partials
#pragma unroll
    for (int e = 0; e < 8; e++) {
        rs[e] += __shfl_xor_sync(0xffffffffu, rs[e], 1);
        rs[e] += __shfl_xor_sync(0xffffffffu, rs[e], 2);
    }
    if ((lane & 3) == 0) {
#pragma unroll
        for (int i = 0; i < 4; i++) {
            rbpart[warp * 64 + i * 16 + r0]     = rs[i * 2];
            rbpart[warp * 64 + i * 16 + r0 + 8] = rs[i * 2 + 1];
        }
    }
    __syncthreads();   // Rs + rbpart complete

    // finalize biases (deterministic 8-way sum)
    if (tid < 64) {
        float s = 0.f;
#pragma unroll
        for (int w = 0; w < 8; w++) s += rbpart[w * 64 + tid];
        rb[tid] = -alpha[0] * s;
    }
    if (tid < P_SZ) bp[tid] = g_biasP[tid];
    __syncthreads();   // rb/bp final

    // ---------------- Phase B: raw mma.sync bf16, 64x32 warp tiles, B prefetched ----------------
    float c2[4][4][4];
#pragma unroll
    for (int i = 0; i < 4; i++)
#pragma unroll
        for (int j = 0; j < 4; j++)
#pragma unroll
            for (int e = 0; e < 4; e++) c2[i][j][e] = 0.f;

    const uint32_t su_rs = smem_u32(Rs);
    const uint32_t arow_off = (uint32_t)(((mtx & 1) * 8 + mrw) * (RS_LD * 2) + (mtx >> 1) * 16);

    uint2 b1r[2][4], b2r[2][4];
#pragma unroll
    for (int j = 0; j < 4; j++) {
        size_t off = ((size_t)(warp * 4 + j) * 32) * 32 + lane;
        b1r[0][j] = g_W1p[off];
        b2r[0][j] = g_W2p[off];
    }

#pragma unroll 8
    for (int kk = 0; kk < 32; kk++) {
        int cur = kk & 1, nxt = cur ^ 1;
        if (kk < 31) {
#pragma unroll
            for (int j = 0; j < 4; j++) {
                size_t off = ((size_t)(warp * 4 + j) * 32 + kk + 1) * 32 + lane;
                b1r[nxt][j] = g_W1p[off];
                b2r[nxt][j] = g_W2p[off];
            }
        }
#pragma unroll
        for (int i = 0; i < 4; i++) {
            uint32_t a0, a1, a2, a3;
            uint32_t addr = su_rs + (uint32_t)(i * 16 * RS_LD * 2 + kk * 32) + arow_off;
            asm volatile("ldmatrix.sync.aligned.m8n8.x4.shared.b16 {%0,%1,%2,%3}, [%4];"
                         : "=r"(a0), "=r"(a1), "=r"(a2), "=r"(a3) : "r"(addr));
#pragma unroll
            for (int j = 0; j < 4; j++)
                asm volatile("mma.sync.aligned.m16n8k16.row.col.f32.bf16.bf16.f32 "
                             "{%0,%1,%2,%3}, {%4,%5,%6,%7}, {%8,%9}, {%0,%1,%2,%3};"
                             : "+f"(c2[i][j][0]), "+f"(c2[i][j][1]),
                               "+f"(c2[i][j][2]), "+f"(c2[i][j][3])
                             : "r"(a0), "r"(a1), "r"(a2), "r"(a3),
                               "r"(b2r[cur][j].x), "r"(b2r[cur][j].y));
            {
                __nv_bfloat162* p0 = reinterpret_cast<__nv_bfloat162*>(&a0);
                __nv_bfloat162* p1 = reinterpret_cast<__nv_bfloat162*>(&a1);
                __nv_bfloat162* p2 = reinterpret_cast<__nv_bfloat162*>(&a2);
                __nv_bfloat162* p3 = reinterpret_cast<__nv_bfloat162*>(&a3);
                *p0 = __hmul2(*p0, *p0); *p1 = __hmul2(*p1, *p1);
                *p2 = __hmul2(*p2, *p2); *p3 = __hmul2(*p3, *p3);
            }
#pragma unroll
            for (int j = 0; j < 4; j++)
                asm volatile("mma.sync.aligned.m16n8k16.row.col.f32.bf16.bf16.f32 "
                             "{%0,%1,%2,%3}, {%4,%5,%6,%7}, {%8,%9}, {%0,%1,%2,%3};"
                             : "+f"(c2[i][j][0]), "+f"(c2[i][j][1]),
                               "+f"(c2[i][j][2]), "+f"(c2[i][j][3])
                             : "r"(a0), "r"(a1), "r"(a2), "r"(a3),
                               "r"(b1r[cur][j].x), "r"(b1r[cur][j].y));
        }
    }

    // ---------------- direct epilogue: accum + rb + bp -> out ----------------
    {
        int ncol = warp * 32;
        float rbv[8], bpv[8];
#pragma unroll
        for (int i = 0; i < 4; i++) {
            rbv[i * 2]     = rb[i * 16 + r0];
            rbv[i * 2 + 1] = rb[i * 16 + r0 + 8];
        }
#pragma unroll
        for (int j = 0; j < 4; j++) {
            bpv[j * 2]     = bp[ncol + j * 8 + cofs];
            bpv[j * 2 + 1] = bp[ncol + j * 8 + cofs + 1];
        }
#pragma unroll
        for (int i = 0; i < 4; i++)
#pragma unroll
            for (int j = 0; j < 4; j++) {
                size_t base1 = (size_t)(m0 + i * 16 + r0) * P_SZ + ncol + j * 8 + cofs;
                *(float2*)(out + base1) =
                    make_float2(c2[i][j][0] + rbv[i * 2] + bpv[j * 2],
                                c2[i][j][1] + rbv[i * 2] + bpv[j * 2 + 1]);
                *(float2*)(out + base1 + 8 * P_SZ) =
                    make_float2(c2[i][j][2] + rbv[i * 2 + 1] + bpv[j * 2],
                                c2[i][j][3] + rbv[i * 2 + 1] + bpv[j * 2 + 1]);
            }
    }
}

// =========================== launch ===========================
extern "C" void kernel_launch(void* const* d_in, const int* in_sizes, int n_in,
                              void* d_out, int out_size) {
    const float* x          = (const float*)d_in[0];
    const float* features   = (const float*)d_in[1];
    const float* prototypes = (const float*)d_in[2];
    const float* alpha      = (const float*)d_in[3];
    const float* beta       = (const float*)d_in[4];
    const float* theta      = (const float*)d_in[5];
    float* out = (float*)d_out;

    cudaFuncSetAttribute(prep_kernel, cudaFuncAttributeMaxDynamicSharedMemorySize, 64 * 1024);
    cudaFuncSetAttribute(fused_kernel, cudaFuncAttributeMaxDynamicSharedMemorySize, SMEM_FUSED);

    prep_kernel<<<16 + 128, 256, 64 * 1024>>>(prototypes, features, alpha, beta, theta);
    fused_kernel<<<B_SZ / 64, 256, SMEM_FUSED>>>(x, alpha, out);
}

// round 16
// speedup vs baseline: 1.7425x; 1.0623x over previous
#include <cuda_runtime.h>
#include <cuda_bf16.h>
#include <cuda_fp16.h>
#include <mma.h>
#include <cstdint>

using namespace nvcuda;

#define B_SZ 65536
#define D_SZ 256
#define F_SZ 512
#define P_SZ 256

// padded smem strides — all row strides odd in 16B units => conflict-free
#define RS_LD  520   // bf16: 1040B = 65 units
#define XS_LD  264   // fp16: 528B  = 33 units
#define PS_LD  260   // pside fp32

// ---------------- scratch (static device globals; no allocations) ----------------
// g_Wp: interleaved W2|W1 in mma.sync m16n8k16 B-fragment layout.
//   [nb=P/8][kb=F/16][lane] -> uint4 { W2 bf16x2 (r0), W2 bf16x2 (r1), W1 r0, W1 r1 }
__device__ uint4  g_Wp[(P_SZ / 8) * (F_SZ / 16) * 32];
// g_Fp2: features fp16 B-fragments, paired: [kb=D/16][nbpair=F/16][lane] -> uint4 {nb even uint2, nb odd uint2}
__device__ uint4  g_Fp2[(D_SZ / 16) * (F_SZ / 16) * 32];
__device__ float  g_pwsPart[2 * P_SZ];   // raw pws partial sums per F-half

__device__ __forceinline__ uint32_t smem_u32(const void* p) {
    uint32_t a;
    asm("{ .reg .u64 t; cvta.to.shared.u64 t, %1; cvt.u32.u64 %0, t; }" : "=r"(a) : "l"(p));
    return a;
}

// ===================== kernel 1: heterogeneous prep =====================
// blocks 0..31: p-side (16 p-rows x one F-half each) + W pack; blocks 32..95: features pack.
__global__ __launch_bounds__(256, 1)
void prep_kernel(const float* __restrict__ prototypes,
                 const float* __restrict__ features,
                 const float* __restrict__ alpha,
                 const float* __restrict__ beta,
                 const float* __restrict__ theta) {
    int tid = threadIdx.x;

    if (blockIdx.x >= 32) {
        // ---- fpack role: 64 CTAs x 256 threads = 16384 uint4 entries ----
        int idx = (blockIdx.x - 32) * 256 + tid;
        int lane   = idx & 31;
        int nbpair = (idx >> 5) & 31;
        int kb     = idx >> 10;            // 0..15
        uint4 w;
#pragma unroll
        for (int e = 0; e < 2; e++) {
            int nb = nbpair * 2 + e;
            int f = nb * 8 + (lane >> 2);
            int k = kb * 16 + (lane & 3) * 2;
            uint2 u2;
#pragma unroll
            for (int r = 0; r < 2; r++) {
                float v0 = features[(size_t)f * D_SZ + k + r * 8];
                float v1 = features[(size_t)f * D_SZ + k + r * 8 + 1];
                __half2 h = __floats2half2_rn(v0, v1);
                uint32_t u = *reinterpret_cast<uint32_t*>(&h);
                if (r == 0) u2.x = u; else u2.y = u;
            }
            if (e == 0) { w.x = u2.x; w.y = u2.y; } else { w.z = u2.x; w.w = u2.y; }
        }
        g_Fp2[idx] = w;
        return;
    }

    // ---- pside role: CTA (pb, fh), pb = blockIdx & 15, fh = blockIdx >> 4 ----
    extern __shared__ float smp[];
    float* ps   = smp;                   // [16][PS_LD]
    float* Outs = smp + 16 * PS_LD;      // [16][256] (one F-half)

    int warp = tid >> 5;
    int lane = tid & 31;
    int pb = blockIdx.x & 15;
    int fh = blockIdx.x >> 4;
    int p0 = pb * 16;
    int fbase = fh * 256;

    {
        const float4* src = (const float4*)(prototypes + (size_t)p0 * D_SZ);
        for (int i = tid; i < 16 * D_SZ / 4; i += 256) {
            int row = i >> 6, q = i & 63;
            ((float4*)(ps + row * PS_LD))[q] = src[(size_t)row * 64 + q];
        }
    }
    __syncthreads();

    using FragA = wmma::fragment<wmma::matrix_a, 16, 16, 8, wmma::precision::tf32, wmma::row_major>;
    using FragB = wmma::fragment<wmma::matrix_b, 16, 16, 8, wmma::precision::tf32, wmma::col_major>;
    using FragC = wmma::fragment<wmma::accumulator, 16, 16, 8, float>;

    FragC c[2];
#pragma unroll
    for (int j = 0; j < 2; j++) wmma::fill_fragment(c[j], 0.f);

    int f0 = fbase + warp * 32;
#pragma unroll 4
    for (int k0 = 0; k0 < D_SZ; k0 += 8) {
        FragA a;
        wmma::load_matrix_sync(a, ps + k0, PS_LD);
#pragma unroll
        for (int e = 0; e < a.num_elements; e++) a.x[e] = wmma::__float_to_tf32(a.x[e]);
#pragma unroll
        for (int j = 0; j < 2; j++) {
            FragB b;
            wmma::load_matrix_sync(b, features + (size_t)(f0 + j * 16) * D_SZ + k0, D_SZ);
#pragma unroll
            for (int e = 0; e < b.num_elements; e++) b.x[e] = wmma::__float_to_tf32(b.x[e]);
            wmma::mma_sync(c[j], a, b, c[j]);
        }
    }
#pragma unroll
    for (int j = 0; j < 2; j++)
        wmma::store_matrix_sync(Outs + warp * 32 + j * 16, c[j], 256, wmma::mem_row_major);
    __syncthreads();

    float a_ = alpha[0], b_ = beta[0], th = theta[0];

    // pack interleaved W fragments: 2 nb x 16 local kb x 32 lanes = 1024 uint4 per CTA
    for (int idx = tid; idx < 1024; idx += 256) {
        int lanep = idx & 31;
        int kbl   = (idx >> 5) & 15;
        int nbl   = idx >> 9;
        int pl = nbl * 8 + (lanep >> 2);
        int fb = kbl * 16 + (lanep & 3) * 2;      // local col within half
        uint4 w;
#pragma unroll
        for (int r = 0; r < 2; r++) {
            float acc0 = Outs[pl * 256 + fb + r * 8];
            float acc1 = Outs[pl * 256 + fb + r * 8 + 1];
            float pp0 = fmaxf(acc0, 0.f), pp1 = fmaxf(acc1, 0.f);
            float pw0 = acc0 * pp0, pw1 = acc1 * pp1;
            __nv_bfloat162 v1 = __floats2bfloat162_rn(th * pw0 + a_ * pp0, th * pw1 + a_ * pp1);
            __nv_bfloat162 v2 = __floats2bfloat162_rn(b_ * pw0, b_ * pw1);
            uint32_t u1 = *reinterpret_cast<uint32_t*>(&v1);
            uint32_t u2 = *reinterpret_cast<uint32_t*>(&v2);
            if (r == 0) { w.x = u2; w.z = u1; } else { w.y = u2; w.w = u1; }
        }
        int nb = pb * 2 + nbl;
        int kbg = fh * 16 + kbl;
        g_Wp[((size_t)nb * 32 + kbg) * 32 + lanep] = w;
    }

    // pws partial over this half (raw sum; beta applied in fused)
    for (int r = warp * 2; r < warp * 2 + 2; r++) {
        float s = 0.f;
        for (int cix = lane; cix < 256; cix += 32) {
            float acc = Outs[r * 256 + cix];
            s += acc * fmaxf(acc, 0.f);
        }
#pragma unroll
        for (int o = 16; o > 0; o >>= 1) s += __shfl_xor_sync(0xffffffffu, s, o);
        if (lane == 0) g_pwsPart[fh * P_SZ + p0 + r] = s;
    }
}

// ===================== kernel 2: fused, 64-row CTAs, 2 CTA/SM =====================
#define RS_BYTES   (64 * RS_LD * 2)                  // 66,560
#define BUF_OFF    RS_BYTES
#define BUF_BYTES  34048                             // xs
#define RB_OFF     (BUF_OFF + BUF_BYTES)
#define BP_OFF     (RB_OFF + 256)
#define RBP_OFF    (BP_OFF + 1024)                   // rbpart fp32[8][64]
#define SMEM_FUSED (RBP_OFF + 2048)                  // ≈ 102 KB

__global__ __launch_bounds__(256, 2)
void fused_kernel(const float* __restrict__ x,
                  const float* __restrict__ alpha,
                  const float* __restrict__ beta,
                  float* __restrict__ out) {
    extern __shared__ char smraw[];
    __nv_bfloat16* Rs     = (__nv_bfloat16*)smraw;
    float*         rb     = (float*)(smraw + RB_OFF);
    float*         bp     = (float*)(smraw + BP_OFF);
    float*         rbpart = (float*)(smraw + RBP_OFF);

    int tid  = threadIdx.x;
    int warp = tid >> 5;
    int lane = tid & 31;
    int m0   = blockIdx.x * 64;

    const int r0   = lane >> 2;
    const int cofs = (lane & 3) * 2;
    const int mtx = lane >> 3, mrw = lane & 7;

    // ---------------- stage x tile as fp16 ----------------
    __half* xs = (__half*)(smraw + BUF_OFF);   // [64][XS_LD]
    {
        const float4* src = (const float4*)(x + (size_t)m0 * D_SZ);
        for (int i = tid; i < 64 * 64; i += 256) {
            int row = i >> 6, q = i & 63;
            float4 v = src[(size_t)row * 64 + q];
            __half2 h0 = __floats2half2_rn(v.x, v.y);
            __half2 h1 = __floats2half2_rn(v.z, v.w);
            uint2 w;
            w.x = *reinterpret_cast<uint32_t*>(&h0);
            w.y = *reinterpret_cast<uint32_t*>(&h1);
            *(uint2*)(xs + row * XS_LD + q * 4) = w;
        }
    }
    __syncthreads();

    // ---------------- Phase A: R = relu(x @ F^T), raw mma.sync f16, paired-B prefetch ----------------
    const uint32_t su_xs = smem_u32(xs);
    const uint32_t xrow_off = (uint32_t)(((mtx & 1) * 8 + mrw) * (XS_LD * 2) + (mtx >> 1) * 16);

    float rs[8];
#pragma unroll
    for (int e = 0; e < 8; e++) rs[e] = 0.f;

    for (int fpass = 0; fpass < 2; fpass++) {
        float c1[4][4][4];
#pragma unroll
        for (int i = 0; i < 4; i++)
#pragma unroll
            for (int j = 0; j < 4; j++)
#pragma unroll
                for (int e = 0; e < 4; e++) c1[i][j][e] = 0.f;

        int f0 = fpass * 256 + warp * 32;
        int nbp0 = f0 >> 4;   // nb pair index

        uint4 bf[2][2];   // [buf][jp]
#pragma unroll
        for (int jp = 0; jp < 2; jp++)
            bf[0][jp] = g_Fp2[((size_t)0 * 32 + nbp0 + jp) * 32 + lane];

#pragma unroll 8
        for (int kk = 0; kk < 16; kk++) {
            int cur = kk & 1, nxt = cur ^ 1;
            if (kk < 15) {
#pragma unroll
                for (int jp = 0; jp < 2; jp++)
                    bf[nxt][jp] = g_Fp2[((size_t)(kk + 1) * 32 + nbp0 + jp) * 32 + lane];
            }
#pragma unroll
            for (int i = 0; i < 4; i++) {
                uint32_t a0, a1, a2, a3;
                uint32_t addr = su_xs + (uint32_t)(i * 16 * XS_LD * 2 + kk * 32) + xrow_off;
                asm volatile("ldmatrix.sync.aligned.m8n8.x4.shared.b16 {%0,%1,%2,%3}, [%4];"
                             : "=r"(a0), "=r"(a1), "=r"(a2), "=r"(a3) : "r"(addr));
#pragma unroll
                for (int jp = 0; jp < 2; jp++) {
                    asm volatile("mma.sync.aligned.m16n8k16.row.col.f32.f16.f16.f32 "
                                 "{%0,%1,%2,%3}, {%4,%5,%6,%7}, {%8,%9}, {%0,%1,%2,%3};"
                                 : "+f"(c1[i][jp * 2][0]), "+f"(c1[i][jp * 2][1]),
                                   "+f"(c1[i][jp * 2][2]), "+f"(c1[i][jp * 2][3])
                                 : "r"(a0), "r"(a1), "r"(a2), "r"(a3),
                                   "r"(bf[cur][jp].x), "r"(bf[cur][jp].y));
                    asm volatile("mma.sync.aligned.m16n8k16.row.col.f32.f16.f16.f32 "
                                 "{%0,%1,%2,%3}, {%4,%5,%6,%7}, {%8,%9}, {%0,%1,%2,%3};"
                                 : "+f"(c1[i][jp * 2 + 1][0]), "+f"(c1[i][jp * 2 + 1][1]),
                                   "+f"(c1[i][jp * 2 + 1][2]), "+f"(c1[i][jp * 2 + 1][3])
                                 : "r"(a0), "r"(a1), "r"(a2), "r"(a3),
                                   "r"(bf[cur][jp].z), "r"(bf[cur][jp].w));
                }
            }
        }

        // direct epilogue: relu (fp32) -> row-sum partials + bf16x2 -> Rs
#pragma unroll
        for (int i = 0; i < 4; i++)
#pragma unroll
            for (int j = 0; j < 4; j++) {
                int col = f0 + j * 8 + cofs;
                float v0 = fmaxf(c1[i][j][0], 0.f), v1 = fmaxf(c1[i][j][1], 0.f);
                float v2 = fmaxf(c1[i][j][2], 0.f), v3 = fmaxf(c1[i][j][3], 0.f);
                rs[i * 2]     += v0 * v0 + v1 * v1;
                rs[i * 2 + 1] += v2 * v2 + v3 * v3;
                __nv_bfloat162 lo = __floats2bfloat162_rn(v0, v1);
                __nv_bfloat162 hi = __floats2bfloat162_rn(v2, v3);
                *reinterpret_cast<uint32_t*>(&Rs[(i * 16 + r0) * RS_LD + col])     = *reinterpret_cast<uint32_t*>(&lo);
                *reinterpret_cast<uint32_t*>(&Rs[(i * 16 + r0 + 8) * RS_LD + col]) = *reinterpret_cast<uint32_t*>(&hi);
            }
    }

#pragma unroll
    for (int e = 0; e < 8; e++) {
        rs[e] += __shfl_xor_sync(0xffffffffu, rs[e], 1);
        rs[e] += __shfl_xor_sync(0xffffffffu, rs[e], 2);
    }
    if ((lane & 3) == 0) {
#pragma unroll
        for (int i = 0; i < 4; i++) {
            rbpart[warp * 64 + i * 16 + r0]     = rs[i * 2];
            rbpart[warp * 64 + i * 16 + r0 + 8] = rs[i * 2 + 1];
        }
    }
    __syncthreads();   // Rs + rbpart complete

    if (tid < 64) {
        float s = 0.f;
#pragma unroll
        for (int w = 0; w < 8; w++) s += rbpart[w * 64 + tid];
        rb[tid] = -alpha[0] * s;
    }
    if (tid < P_SZ) bp[tid] = -beta[0] * (g_pwsPart[tid] + g_pwsPart[P_SZ + tid]);
    __syncthreads();   // rb/bp final

    // ---------------- Phase B: raw mma.sync bf16, 64x32 warp tiles, uint4 W prefetch ----------------
    float c2[4][4][4];
#pragma unroll
    for (int i = 0; i < 4; i++)
#pragma unroll
        for (int j = 0; j < 4; j++)
#pragma unroll
            for (int e = 0; e < 4; e++) c2[i][j][e] = 0.f;

    const uint32_t su_rs = smem_u32(Rs);
    const uint32_t arow_off = (uint32_t)(((mtx & 1) * 8 + mrw) * (RS_LD * 2) + (mtx >> 1) * 16);

    uint4 b12[2][4];   // [buf][j]: {W2.x, W2.y, W1.x, W1.y}
#pragma unroll
    for (int j = 0; j < 4; j++)
        b12[0][j] = g_Wp[((size_t)(warp * 4 + j) * 32) * 32 + lane];

#pragma unroll 8
    for (int kk = 0; kk < 32; kk++) {
        int cur = kk & 1, nxt = cur ^ 1;
        if (kk < 31) {
#pragma unroll
            for (int j = 0; j < 4; j++)
                b12[nxt][j] = g_Wp[((size_t)(warp * 4 + j) * 32 + kk + 1) * 32 + lane];
        }
#pragma unroll
        for (int i = 0; i < 4; i++) {
            uint32_t a0, a1, a2, a3;
            uint32_t addr = su_rs + (uint32_t)(i * 16 * RS_LD * 2 + kk * 32) + arow_off;
            asm volatile("ldmatrix.sync.aligned.m8n8.x4.shared.b16 {%0,%1,%2,%3}, [%4];"
                         : "=r"(a0), "=r"(a1), "=r"(a2), "=r"(a3) : "r"(addr));
#pragma unroll
            for (int j = 0; j < 4; j++)
                asm volatile("mma.sync.aligned.m16n8k16.row.col.f32.bf16.bf16.f32 "
                             "{%0,%1,%2,%3}, {%4,%5,%6,%7}, {%8,%9}, {%0,%1,%2,%3};"
                             : "+f"(c2[i][j][0]), "+f"(c2[i][j][1]),
                               "+f"(c2[i][j][2]), "+f"(c2[i][j][3])
                             : "r"(a0), "r"(a1), "r"(a2), "r"(a3),
                               "r"(b12[cur][j].x), "r"(b12[cur][j].y));
            {
                __nv_bfloat162* p0 = reinterpret_cast<__nv_bfloat162*>(&a0);
                __nv_bfloat162* p1 = reinterpret_cast<__nv_bfloat162*>(&a1);
                __nv_bfloat162* p2 = reinterpret_cast<__nv_bfloat162*>(&a2);
                __nv_bfloat162* p3 = reinterpret_cast<__nv_bfloat162*>(&a3);
                *p0 = __hmul2(*p0, *p0); *p1 = __hmul2(*p1, *p1);
                *p2 = __hmul2(*p2, *p2); *p3 = __hmul2(*p3, *p3);
            }
#pragma unroll
            for (int j = 0; j < 4; j++)
                asm volatile("mma.sync.aligned.m16n8k16.row.col.f32.bf16.bf16.f32 "
                             "{%0,%1,%2,%3}, {%4,%5,%6,%7}, {%8,%9}, {%0,%1,%2,%3};"
                             : "+f"(c2[i][j][0]), "+f"(c2[i][j][1]),
                               "+f"(c2[i][j][2]), "+f"(c2[i][j][3])
                             : "r"(a0), "r"(a1), "r"(a2), "r"(a3),
                               "r"(b12[cur][j].z), "r"(b12[cur][j].w));
        }
    }

    // ---------------- direct epilogue: accum + rb + bp -> out ----------------
    {
        int ncol = warp * 32;
        float rbv[8], bpv[8];
#pragma unroll
        for (int i = 0; i < 4; i++) {
            rbv[i * 2]     = rb[i * 16 + r0];
            rbv[i * 2 + 1] = rb[i * 16 + r0 + 8];
        }
#pragma unroll
        for (int j = 0; j < 4; j++) {
            bpv[j * 2]     = bp[ncol + j * 8 + cofs];
            bpv[j * 2 + 1] = bp[ncol + j * 8 + cofs + 1];
        }
#pragma unroll
        for (int i = 0; i < 4; i++)
#pragma unroll
            for (int j = 0; j < 4; j++) {
                size_t base1 = (size_t)(m0 + i * 16 + r0) * P_SZ + ncol + j * 8 + cofs;
                *(float2*)(out + base1) =
                    make_float2(c2[i][j][0] + rbv[i * 2] + bpv[j * 2],
                                c2[i][j][1] + rbv[i * 2] + bpv[j * 2 + 1]);
                *(float2*)(out + base1 + 8 * P_SZ) =
                    make_float2(c2[i][j][2] + rbv[i * 2 + 1] + bpv[j * 2],
                                c2[i][j][3] + rbv[i * 2 + 1] + bpv[j * 2 + 1]);
            }
    }
}

// =========================== launch ===========================
extern "C" void kernel_launch(void* const* d_in, const int* in_sizes, int n_in,
                              void* d_out, int out_size) {
    const float* x          = (const float*)d_in[0];
    const float* features   = (const float*)d_in[1];
    const float* prototypes = (const float*)d_in[2];
    const float* alpha      = (const float*)d_in[3];
    const float* beta       = (const float*)d_in[4];
    const float* theta      = (const float*)d_in[5];
    float* out = (float*)d_out;

    cudaFuncSetAttribute(prep_kernel, cudaFuncAttributeMaxDynamicSharedMemorySize, 34 * 1024);
    cudaFuncSetAttribute(fused_kernel, cudaFuncAttributeMaxDynamicSharedMemorySize, SMEM_FUSED);

    prep_kernel<<<32 + 64, 256, 34 * 1024>>>(prototypes, features, alpha, beta, theta);
    fused_kernel<<<B_SZ / 64, 256, SMEM_FUSED>>>(x, alpha, beta, out);
}